// round 1
// baseline (speedup 1.0000x reference)
#include <cuda_runtime.h>

// ---------------------------------------------------------------------------
// Static geometry (matches reference)
// ---------------------------------------------------------------------------
#define Bc    16
#define NPp   4096
#define Mm    1024
#define NCc   (Bc * Mm)      /* 16384 centers  */
#define NPTS  (Bc * NPp)     /* 65536 points   */
#define CINc  64
#define HIDc  64
#define OUTCc 128
#define Kk    64
#define R2f   0.04f
#define CAPn  512

// ---------------------------------------------------------------------------
// Device scratch (no runtime allocation allowed)
// ---------------------------------------------------------------------------
__device__ float  g_centers[NCc * 3];
__device__ int    g_nidx[NCc * Kk];
__device__ float4 g_F1[NPTS * (HIDc / 4)];   // F1 = feat @ W1[:64] + b1, row-major [NPTS][64]

// ---------------------------------------------------------------------------
// Kernel 1: farthest point sampling, one block per cloud.
// Exactly reproduces: d0 = |p - p0|^2 ; loop: nxt = argmax(d) (tie -> lowest
// index), d = min(d, |p - p_nxt|^2).
// ---------------------------------------------------------------------------
__global__ __launch_bounds__(1024) void fps_kernel(const float* __restrict__ point)
{
    const int b    = blockIdx.x;
    const int t    = threadIdx.x;
    const int lane = t & 31;
    const int w    = t >> 5;
    const float* pc = point + (long)b * NPp * 3;

    __shared__ float rx[32], ry[32], rz[32], rd[32];
    __shared__ int   ri[32];
    __shared__ float bc[3];

    const float x0 = pc[0], y0 = pc[1], z0 = pc[2];
    float px[4], py[4], pz[4], d[4];
#pragma unroll
    for (int u = 0; u < 4; u++) {
        const int gi = t * 4 + u;
        px[u] = pc[gi * 3 + 0];
        py[u] = pc[gi * 3 + 1];
        pz[u] = pc[gi * 3 + 2];
        const float dx = px[u] - x0, dy = py[u] - y0, dz = pz[u] - z0;
        d[u] = dx * dx + dy * dy + dz * dz;
    }
    if (t == 0) {
        g_centers[(b * Mm) * 3 + 0] = x0;
        g_centers[(b * Mm) * 3 + 1] = y0;
        g_centers[(b * Mm) * 3 + 2] = z0;
    }

    for (int m = 1; m < Mm; m++) {
        // ---- local argmax over 4 owned points (strict > keeps lowest index)
        float bd = -1.0f, bx = 0.f, by = 0.f, bz = 0.f;
        int   bi = 0x7fffffff;
#pragma unroll
        for (int u = 0; u < 4; u++) {
            if (d[u] > bd) { bd = d[u]; bi = t * 4 + u; bx = px[u]; by = py[u]; bz = pz[u]; }
        }
        // ---- warp reduce (tie-break: lower index wins)
#pragma unroll
        for (int o = 16; o > 0; o >>= 1) {
            const float od = __shfl_down_sync(0xffffffffu, bd, o);
            const int   oi = __shfl_down_sync(0xffffffffu, bi, o);
            const float ox = __shfl_down_sync(0xffffffffu, bx, o);
            const float oy = __shfl_down_sync(0xffffffffu, by, o);
            const float oz = __shfl_down_sync(0xffffffffu, bz, o);
            if (od > bd || (od == bd && oi < bi)) { bd = od; bi = oi; bx = ox; by = oy; bz = oz; }
        }
        if (lane == 0) { rd[w] = bd; ri[w] = bi; rx[w] = bx; ry[w] = by; rz[w] = bz; }
        __syncthreads();
        if (w == 0) {
            bd = rd[lane]; bi = ri[lane]; bx = rx[lane]; by = ry[lane]; bz = rz[lane];
#pragma unroll
            for (int o = 16; o > 0; o >>= 1) {
                const float od = __shfl_down_sync(0xffffffffu, bd, o);
                const int   oi = __shfl_down_sync(0xffffffffu, bi, o);
                const float ox = __shfl_down_sync(0xffffffffu, bx, o);
                const float oy = __shfl_down_sync(0xffffffffu, by, o);
                const float oz = __shfl_down_sync(0xffffffffu, bz, o);
                if (od > bd || (od == bd && oi < bi)) { bd = od; bi = oi; bx = ox; by = oy; bz = oz; }
            }
            if (lane == 0) {
                bc[0] = bx; bc[1] = by; bc[2] = bz;
                g_centers[(b * Mm + m) * 3 + 0] = bx;
                g_centers[(b * Mm + m) * 3 + 1] = by;
                g_centers[(b * Mm + m) * 3 + 2] = bz;
            }
        }
        __syncthreads();
        const float cx = bc[0], cy = bc[1], cz = bc[2];
#pragma unroll
        for (int u = 0; u < 4; u++) {
            const float dx = px[u] - cx, dy = py[u] - cy, dz = pz[u] - cz;
            d[u] = fminf(d[u], dx * dx + dy * dy + dz * dz);
        }
    }
}

// ---------------------------------------------------------------------------
// Kernel 2: F1 = xyz @ W1[:64,:] + b1   (pre-relu, feature half of layer 1)
// One block computes a 64-row tile.
// ---------------------------------------------------------------------------
__global__ __launch_bounds__(128) void f1_kernel(const float* __restrict__ xyz,
                                                 const float* __restrict__ W1,
                                                 const float* __restrict__ b1)
{
    __shared__ alignas(16) float sA[64 * 64];
    __shared__ alignas(16) float sW[64 * 64];
    __shared__ float sb[64];
    const int tid  = threadIdx.x;
    const int row0 = blockIdx.x * 64;

    for (int i = tid; i < 64 * 16; i += 128) {
        const int r = i >> 4, c4 = (i & 15) << 2;
        *(float4*)&sA[r * 64 + c4] = *(const float4*)&xyz[(long)(row0 + r) * 64 + c4];
        *(float4*)&sW[r * 64 + c4] = *(const float4*)&W1[r * 64 + c4];
    }
    if (tid < 64) sb[tid] = b1[tid];
    __syncthreads();

    const int r0 = (tid >> 4) * 8, c0 = (tid & 15) * 4;
    float acc[8][4];
#pragma unroll
    for (int r = 0; r < 8; r++)
#pragma unroll
        for (int c = 0; c < 4; c++) acc[r][c] = sb[c0 + c];

    for (int kk = 0; kk < 64; kk += 4) {
        float wr[4][4];
#pragma unroll
        for (int jj = 0; jj < 4; jj++)
            *(float4*)wr[jj] = *(float4*)&sW[(kk + jj) * 64 + c0];
#pragma unroll
        for (int r = 0; r < 8; r++) {
            float am[4];
            *(float4*)am = *(float4*)&sA[(r0 + r) * 64 + kk];
#pragma unroll
            for (int c = 0; c < 4; c++)
#pragma unroll
                for (int jj = 0; jj < 4; jj++)
                    acc[r][c] = fmaf(am[jj], wr[jj][c], acc[r][c]);
        }
    }
#pragma unroll
    for (int r = 0; r < 8; r++) {
        float4 v = make_float4(acc[r][0], acc[r][1], acc[r][2], acc[r][3]);
        g_F1[((long)(row0 + r0 + r) * 64 + c0) >> 2] = v;
    }
}

// ---------------------------------------------------------------------------
// Kernel 3: neighbor selection. One warp per center. K nearest in-ball with
// (d2, idx) lexicographic tie-break (== reference top_k semantics). Slots past
// the valid count are padded with neighbor 0 (the center itself, d2 = 0),
// which makes downstream max-aggregation mask-free.
// ---------------------------------------------------------------------------
__global__ __launch_bounds__(256) void neigh_kernel(const float* __restrict__ point)
{
    __shared__ unsigned long long skey[8][CAPn];
    __shared__ int scnt[8];
    __shared__ int ssel[8][Kk];

    const int w    = threadIdx.x >> 5;
    const int lane = threadIdx.x & 31;
    const int cid  = blockIdx.x * 8 + w;
    const int b    = cid >> 10;
    const int base = b << 12;

    if (lane == 0) scnt[w] = 0;
    __syncwarp();

    const float cx = g_centers[cid * 3 + 0];
    const float cy = g_centers[cid * 3 + 1];
    const float cz = g_centers[cid * 3 + 2];

    for (int p = lane; p < NPp; p += 32) {
        const float* pp = point + (long)(base + p) * 3;
        const float dx = cx - pp[0], dy = cy - pp[1], dz = cz - pp[2];
        const float d2 = dx * dx + dy * dy + dz * dz;
        if (d2 < R2f) {
            const int pos = atomicAdd(&scnt[w], 1);
            if (pos < CAPn)
                skey[w][pos] = ((unsigned long long)__float_as_uint(d2) << 32) | (unsigned)p;
        }
    }
    __syncwarp();

    const int n = min(scnt[w], CAPn);
    for (int e = lane; e < n; e += 32) {
        const unsigned long long ke = skey[w][e];
        int r = 0;
        for (int f = 0; f < n; f++) r += (skey[w][f] < ke);
        if (r < Kk) ssel[w][r] = base + (int)(ke & 0xffffffffu);
    }
    __syncwarp();
    const int sc = min(n, Kk);               // >= 1 always (center is in its own ball)
    for (int r = sc + lane; r < Kk; r += 32) ssel[w][r] = ssel[w][0];
    __syncwarp();
    for (int r = lane; r < Kk; r += 32) g_nidx[cid * Kk + r] = ssel[w][r];
}

// ---------------------------------------------------------------------------
// Kernel 4: fused per-center MLP + max aggregation.
// Block = 128 threads, processes 8 centers sequentially (weights staged once).
// ---------------------------------------------------------------------------
__global__ __launch_bounds__(128) void mlp_kernel(const float* __restrict__ point,
                                                  const float* __restrict__ W1,
                                                  const float* __restrict__ W2,
                                                  const float* __restrict__ b2,
                                                  const float* __restrict__ W3,
                                                  const float* __restrict__ b3,
                                                  float* __restrict__ out)
{
    extern __shared__ float smem[];
    float* sW2   = smem;                  // 4096
    float* sW3   = sW2 + 4096;            // 8192
    float* sW1b  = sW3 + 8192;            // 192   (W1 rows 64..66)
    float* sb2   = sW1b + 192;            // 64
    float* sb3   = sb2 + 64;              // 128
    float* sH1   = sb3 + 128;             // 64*68
    float* sH2   = sH1 + 64 * 68;         // 64*68
    float* sOut  = sH2 + 64 * 68;         // 128
    int*   snb   = (int*)(sOut + 128);    // 64
    float* scent = (float*)(snb + 64);    // 4

    const int tid = threadIdx.x;
    for (int i = tid; i < 1024; i += 128) ((float4*)sW2)[i] = ((const float4*)W2)[i];
    for (int i = tid; i < 2048; i += 128) ((float4*)sW3)[i] = ((const float4*)W3)[i];
    for (int i = tid; i < 192; i += 128) sW1b[i] = W1[4096 + i];
    if (tid < 64) sb2[tid] = b2[tid];
    sb3[tid] = b3[tid];
    __syncthreads();

    for (int cc = 0; cc < 8; cc++) {
        const int cid = blockIdx.x * 8 + cc;
        if (tid < 64) snb[tid] = g_nidx[cid * Kk + tid];
        if (tid < 3)  scent[tid] = g_centers[cid * 3 + tid];
        sOut[tid] = 0.0f;
        __syncthreads();

        // ---- stage 1: H1[k][c] = relu(F1[j_k][c] + dpos_k . W1b[:,c])
        {
            const int k = tid >> 1, half = tid & 1;
            const int j = snb[k];
            const float dx = point[(long)j * 3 + 0] - scent[0];
            const float dy = point[(long)j * 3 + 1] - scent[1];
            const float dz = point[(long)j * 3 + 2] - scent[2];
            const float4* frow = &g_F1[(long)j * 16 + half * 8];
            float* hrow = &sH1[k * 68 + half * 32];
#pragma unroll
            for (int q = 0; q < 8; q++) {
                float4 f = frow[q];
                const int c = half * 32 + q * 4;
                const float4 wa = *(float4*)&sW1b[c];
                const float4 wb = *(float4*)&sW1b[64 + c];
                const float4 wc = *(float4*)&sW1b[128 + c];
                f.x = fmaxf(fmaf(dx, wa.x, fmaf(dy, wb.x, fmaf(dz, wc.x, f.x))), 0.f);
                f.y = fmaxf(fmaf(dx, wa.y, fmaf(dy, wb.y, fmaf(dz, wc.y, f.y))), 0.f);
                f.z = fmaxf(fmaf(dx, wa.z, fmaf(dy, wb.z, fmaf(dz, wc.z, f.z))), 0.f);
                f.w = fmaxf(fmaf(dx, wa.w, fmaf(dy, wb.w, fmaf(dz, wc.w, f.w))), 0.f);
                *(float4*)&hrow[q * 4] = f;
            }
        }
        __syncthreads();

        // ---- stage 2: H2 = relu(H1 @ W2 + b2), 8x4 register tile
        {
            const int r0 = (tid >> 4) * 8, c0 = (tid & 15) * 4;
            float acc[8][4];
#pragma unroll
            for (int r = 0; r < 8; r++)
#pragma unroll
                for (int c = 0; c < 4; c++) acc[r][c] = sb2[c0 + c];
            for (int kk = 0; kk < 64; kk += 4) {
                float wr[4][4];
#pragma unroll
                for (int jj = 0; jj < 4; jj++)
                    *(float4*)wr[jj] = *(float4*)&sW2[(kk + jj) * 64 + c0];
#pragma unroll
                for (int r = 0; r < 8; r++) {
                    float am[4];
                    *(float4*)am = *(float4*)&sH1[(r0 + r) * 68 + kk];
#pragma unroll
                    for (int c = 0; c < 4; c++)
#pragma unroll
                        for (int jj = 0; jj < 4; jj++)
                            acc[r][c] = fmaf(am[jj], wr[jj][c], acc[r][c]);
                }
            }
#pragma unroll
            for (int r = 0; r < 8; r++) {
                float4 v = make_float4(fmaxf(acc[r][0], 0.f), fmaxf(acc[r][1], 0.f),
                                       fmaxf(acc[r][2], 0.f), fmaxf(acc[r][3], 0.f));
                *(float4*)&sH2[(r0 + r) * 68 + c0] = v;
            }
        }
        __syncthreads();

        // ---- stage 3: H3 = relu(H2 @ W3 + b3), fused max over k, 8x8 tile
        {
            const int r0 = (tid >> 4) * 8, c0 = (tid & 15) * 8;
            float acc[8][8];
#pragma unroll
            for (int r = 0; r < 8; r++)
#pragma unroll
                for (int c = 0; c < 8; c++) acc[r][c] = sb3[c0 + c];
            for (int kk = 0; kk < 64; kk += 4) {
                float wr[4][8];
#pragma unroll
                for (int jj = 0; jj < 4; jj++) {
                    *(float4*)&wr[jj][0] = *(float4*)&sW3[(kk + jj) * 128 + c0];
                    *(float4*)&wr[jj][4] = *(float4*)&sW3[(kk + jj) * 128 + c0 + 4];
                }
#pragma unroll
                for (int r = 0; r < 8; r++) {
                    float am[4];
                    *(float4*)am = *(float4*)&sH2[(r0 + r) * 68 + kk];
#pragma unroll
                    for (int c = 0; c < 8; c++)
#pragma unroll
                        for (int jj = 0; jj < 4; jj++)
                            acc[r][c] = fmaf(am[jj], wr[jj][c], acc[r][c]);
                }
            }
#pragma unroll
            for (int c = 0; c < 8; c++) {
                float mx = 0.0f;                          // relu floor; >=1 valid neighbor
#pragma unroll
                for (int r = 0; r < 8; r++) mx = fmaxf(mx, acc[r][c]);
                atomicMax((int*)&sOut[c0 + c], __float_as_int(mx));  // mx >= 0 -> int order ok
            }
        }
        __syncthreads();
        out[(long)cid * OUTCc + tid] = sOut[tid];
        __syncthreads();
    }
}

// ---------------------------------------------------------------------------
// Kernel 5: optional tail outputs (centers as f32, batch ids as f32)
// ---------------------------------------------------------------------------
__global__ void tail_kernel(float* __restrict__ out, int out_size)
{
    const int i = blockIdx.x * blockDim.x + threadIdx.x;
    const long base = (long)NCc * OUTCc;
    if (i < NCc * 3 && base + i < out_size) out[base + i] = g_centers[i];
    if (i < NCc && base + NCc * 3 + i < out_size) out[base + NCc * 3 + i] = (float)(i >> 10);
}

// ---------------------------------------------------------------------------
extern "C" void kernel_launch(void* const* d_in, const int* in_sizes, int n_in,
                              void* d_out, int out_size)
{
    const float* xyz   = (const float*)d_in[0];
    const float* point = (const float*)d_in[1];
    // d_in[2] = batch (contiguous, implied), d_in[3] = num_samples (static 64)
    const float* W1 = (const float*)d_in[4];
    const float* b1 = (const float*)d_in[5];
    const float* W2 = (const float*)d_in[6];
    const float* b2 = (const float*)d_in[7];
    const float* W3 = (const float*)d_in[8];
    const float* b3 = (const float*)d_in[9];
    float* out = (float*)d_out;

    const size_t smem = (size_t)(4096 + 8192 + 192 + 64 + 128 + 64 * 68 + 64 * 68 + 128 + 64 + 4) * sizeof(float);
    cudaFuncSetAttribute(mlp_kernel, cudaFuncAttributeMaxDynamicSharedMemorySize, (int)smem);

    fps_kernel<<<Bc, 1024>>>(point);
    f1_kernel<<<NPTS / 64, 128>>>(xyz, W1, b1);
    neigh_kernel<<<NCc / 8, 256>>>(point);
    mlp_kernel<<<NCc / 8, 128, smem>>>(point, W1, W2, b2, W3, b3, out);

    if ((long)out_size > (long)NCc * OUTCc) {
        const int n = NCc * 3;
        tail_kernel<<<(n + 255) / 256, 256>>>(out, out_size);
    }
}